// round 10
// baseline (speedup 1.0000x reference)
#include <cuda_runtime.h>
#include <cuda_bf16.h>
#include <cstdint>
#include <cstddef>

// Problem constants (fixed by the reference)
#define NROWS 8192
#define NCOLS 8192
#define RB 32
#define CB 32
#define HID 100
#define DIO (RB*CB)
#define SPLITS 32                      // row-slots per (rb,cb) block
#define NITEMS (RB*CB*SPLITS)          // 32768 per-warp work items
#define NB_CTAS (148*2)                // 296, all co-resident (2 CTAs/SM)

#define BUF_W4 104                     // max block body width in float4 (416 floats)
#define BURST 8                        // rows staged per burst
#define WARP_BUF4 (BURST*BUF_W4)       // 832 float4 per warp
#define SMEM_BYTES (8*WARP_BUF4*16)    // 106496 B dynamic smem per CTA

// Scratch (no cudaMalloc allowed)
__device__ float g_blk[RB*CB];
__device__ int   g_rowb[RB+1];
__device__ int   g_colb[CB+1];
__device__ int   g_work;
__device__ unsigned g_bar_arrive = 0;
__device__ volatile unsigned g_bar_gen = 0;

__device__ __forceinline__ void cp16(unsigned dst_smem, const void* src) {
    asm volatile("cp.async.ca.shared.global [%0], [%1], 16;" :: "r"(dst_smem), "l"(src));
}

// Generation-based grid barrier: safe across graph replays, deadlock-free
// because all NB_CTAS are co-resident (smem + launch_bounds force 2/SM).
__device__ __forceinline__ void grid_barrier() {
    __syncthreads();
    if (threadIdx.x == 0) {
        __threadfence();
        unsigned gen = g_bar_gen;
        unsigned a = atomicAdd(&g_bar_arrive, 1u);
        if (a == NB_CTAS - 1u) {
            atomicExch(&g_bar_arrive, 0u);
            __threadfence();
            g_bar_gen = gen + 1u;
        } else {
            while (g_bar_gen == gen) { }
            __threadfence();
        }
    }
    __syncthreads();
}

__global__ __launch_bounds__(256, 2)
void k_fused(const float* __restrict__ X,
             const int* __restrict__ row_ids,
             const int* __restrict__ col_ids,
             const float* __restrict__ W1, const float* __restrict__ b1,
             const float* __restrict__ W2, const float* __restrict__ b2,
             const float* __restrict__ W3, const float* __restrict__ b3,
             float* __restrict__ out) {
    extern __shared__ float4 dynbuf4[];
    __shared__ int srow[RB + 1];
    __shared__ int scol[CB + 1];

    const int t = threadIdx.x;
    const int warp = t >> 5, lane = t & 31;

    // ---------------- Phase A: setup (distributed) ----------------
    if (blockIdx.x < 32) {
        const bool rowpass = (blockIdx.x < 16);
        const int  slice   = rowpass ? blockIdx.x : (blockIdx.x - 16);
        const int  nb  = rowpass ? RB : CB;
        const int  n   = rowpass ? NROWS : NCOLS;
        const int* ids = rowpass ? row_ids : col_ids;
        int*   bnd = rowpass ? g_rowb : g_colb;
        float* o   = out + DIO + (rowpass ? 0 : (RB + 1));
        const int i = slice * 512 + t * 2;
        #pragma unroll
        for (int d = 0; d < 2; d++) {
            int g = i + d;
            if (g < n) {
                int cur  = ids[g];
                int prev = (g == 0) ? -1 : ids[g - 1];
                for (int k = prev + 1; k <= cur; k++) { bnd[k] = g; o[k] = (float)g; }
                if (g == n - 1)
                    for (int k = cur + 1; k <= nb; k++) { bnd[k] = n; o[k] = (float)n; }
            }
        }
    } else if (blockIdx.x == 32) {
        for (int j = t; j < DIO; j += 256) g_blk[j] = 0.0f;
    } else if (blockIdx.x == 33 && t == 0) {
        g_work = 0;
    }

    grid_barrier();

    if (t <= RB) srow[t] = g_rowb[t];
    else if (t >= 64 && t <= 64 + CB) scol[t - 64] = g_colb[t - 64];
    __syncthreads();

    // ---------------- Phase B: cp.async-staged per-warp block-sum ----------------
    {
        const float4* Xf4 = (const float4*)X;
        // per-warp smem buffer
        float* bufF = (float*)(dynbuf4 + (size_t)warp * WARP_BUF4);
        unsigned sbase = (unsigned)__cvta_generic_to_shared(dynbuf4 + (size_t)warp * WARP_BUF4);

        int item;
        if (lane == 0) item = atomicAdd(&g_work, 1);
        item = __shfl_sync(0xFFFFFFFFu, item, 0);

        while (item < NITEMS) {
            int next;
            if (lane == 0) next = atomicAdd(&g_work, 1);
            next = __shfl_sync(0xFFFFFFFFu, next, 0);

            const int rb = item >> 10;
            const int cb = (item >> 5) & 31;
            const int ws = item & (SPLITS - 1);
            const int rlo = srow[rb], rhi = srow[rb + 1];
            const int clo = scol[cb], chi = scol[cb + 1];

            const int c4a   = clo >> 2;          // first float4 (16B-aligned floor)
            const int c4b   = (chi + 3) >> 2;    // last float4 (ceil)
            const int W4    = c4b - c4a;
            const int off0  = clo & 3;           // float offset into buffer row
            const int count = chi - clo;

            float acc = 0.f;

            if (W4 <= BUF_W4) {
                int r = rlo + ws;
                while (r < rhi) {
                    // issue burst of up to BURST rows into smem
                    int nb = 0;
                    for (; nb < BURST && r + nb * SPLITS < rhi; nb++) {
                        const float4* src = Xf4 + (size_t)(r + nb * SPLITS) * (NCOLS/4) + c4a;
                        unsigned dst = sbase + nb * (BUF_W4 * 16);
                        for (int k = lane; k < W4; k += 32)
                            cp16(dst + k * 16, src + k);
                    }
                    asm volatile("cp.async.commit_group;" ::: "memory");
                    asm volatile("cp.async.wait_group 0;" ::: "memory");
                    __syncwarp();
                    // reduce the staged rows from smem (exact [clo,chi) range)
                    for (int i = 0; i < nb; i++) {
                        const float* bf = bufF + i * (BUF_W4 * 4) + off0;
                        for (int j = lane; j < count; j += 32) acc += bf[j];
                    }
                    __syncwarp();   // buffer reuse safety before next burst
                    r += nb * SPLITS;
                }
            } else {
                // fallback (block wider than buffer) — direct loads, rare/never
                for (int r = rlo + ws; r < rhi; r += SPLITS) {
                    const float* q = X + (size_t)r * NCOLS;
                    for (int j = clo + lane; j < chi; j += 32) acc += q[j];
                }
            }

            #pragma unroll
            for (int o = 16; o; o >>= 1) acc += __shfl_xor_sync(0xFFFFFFFFu, acc, o);
            if (lane == 0) atomicAdd(&g_blk[rb * CB + cb], acc);

            item = next;
        }
    }

    grid_barrier();

    // ---------------- Phase C: MLP (CTA 0 only), in dynamic smem ----------------
    if (blockIdx.x != 0) return;

    float* dynf = (float*)dynbuf4;
    float* xs  = dynf;            // 1024
    float* h1p = dynf + 1024;     // 800
    float* h2p = h1p + 800;       // 1000
    float* h1  = h2p + 1000;      // 100
    float* h2  = h1 + HID;        // 100

    #pragma unroll
    for (int d = 0; d < 4; d++) {
        int b = t + d * 256;
        int rb = b >> 5, cbi = b & 31;
        float rc = (float)(srow[rb + 1] - srow[rb]);
        float cc = (float)(scol[cbi + 1] - scol[cbi]);
        float cnt = fmaxf(rc * cc, 1.0f);
        xs[b] = g_blk[b] / cnt;
    }
    __syncthreads();

    // layer 1: h1 = relu(x @ W1 + b1), x[1024], W1[1024,100]; 8 K-slices x 100
    for (int u = t; u < 800; u += 256) {
        const int j  = u % HID;
        const int i0 = (u / HID) * 128;
        float acc = 0.f;
        #pragma unroll 8
        for (int i = 0; i < 128; i++)
            acc += xs[i0 + i] * W1[(size_t)(i0 + i) * HID + j];
        h1p[u] = acc;
    }
    __syncthreads();
    if (t < HID) {
        float a = b1[t];
        #pragma unroll
        for (int sl = 0; sl < 8; sl++) a += h1p[sl * HID + t];
        h1[t] = fmaxf(a, 0.f);
    }
    __syncthreads();

    // layer 2: h2 = relu(h1 @ W2 + b2), W2[100,100]; 10 K-slices x 100
    for (int u = t; u < 1000; u += 256) {
        const int j  = u % HID;
        const int i0 = (u / HID) * 10;
        float acc = 0.f;
        #pragma unroll
        for (int i = 0; i < 10; i++)
            acc += h1[i0 + i] * W2[(i0 + i) * HID + j];
        h2p[u] = acc;
    }
    __syncthreads();
    if (t < HID) {
        float a = b2[t];
        #pragma unroll
        for (int sl = 0; sl < 10; sl++) a += h2p[sl * HID + t];
        h2[t] = fmaxf(a, 0.f);
    }
    __syncthreads();

    // layer 3: out = sigmoid(h2 @ W3 + b3), W3[100,1024]
    #pragma unroll
    for (int d = 0; d < 4; d++) {
        int j = t + d * 256;
        float a = b3[j];
        #pragma unroll 10
        for (int i = 0; i < HID; i++) a += h2[i] * W3[(size_t)i * DIO + j];
        out[j] = 1.0f / (1.0f + __expf(-a));
    }
}

extern "C" void kernel_launch(void* const* d_in, const int* in_sizes, int n_in,
                              void* d_out, int out_size) {
    const float* X       = (const float*)d_in[0];
    const int*   row_ids = (const int*)  d_in[1];
    const int*   col_ids = (const int*)  d_in[2];
    const float* W1      = (const float*)d_in[3];
    const float* b1      = (const float*)d_in[4];
    const float* W2      = (const float*)d_in[5];
    const float* b2      = (const float*)d_in[6];
    const float* W3      = (const float*)d_in[7];
    const float* b3      = (const float*)d_in[8];
    float* out = (float*)d_out;

    cudaFuncSetAttribute(k_fused, cudaFuncAttributeMaxDynamicSharedMemorySize,
                         SMEM_BYTES);
    k_fused<<<NB_CTAS, 256, SMEM_BYTES>>>(X, row_ids, col_ids,
                                          W1, b1, W2, b2, W3, b3, out);
}

// round 12
// speedup vs baseline: 1.3350x; 1.3350x over previous
#include <cuda_runtime.h>
#include <cuda_bf16.h>
#include <cstdint>
#include <cstddef>

// Problem constants (fixed by the reference)
#define NROWS 8192
#define NCOLS 8192
#define NC4   (NCOLS/4)                // 2048 float4 per row
#define RB 32
#define CB 32
#define HID 100
#define DIO (RB*CB)
#define NB_CTAS 256                    // grid; all co-resident (2 CTAs/SM cap = 296)

// Scratch (no cudaMalloc allowed)
__device__ float4 g_rowsum4[RB * NC4];   // 1 MB: per-row-block column sums
__device__ float  g_blk[DIO];
__device__ int    g_rowb[RB + 1];
__device__ int    g_colb[CB + 1];
__device__ unsigned g_bar_arrive = 0;
__device__ volatile unsigned g_bar_gen = 0;

// Generation-based grid barrier: safe across graph replays (self-resetting),
// deadlock-free because all NB_CTAS are co-resident (<=2 CTAs/SM by bounds).
__device__ __forceinline__ void grid_barrier() {
    __syncthreads();
    if (threadIdx.x == 0) {
        __threadfence();
        unsigned gen = g_bar_gen;
        unsigned a = atomicAdd(&g_bar_arrive, 1u);
        if (a == NB_CTAS - 1u) {
            atomicExch(&g_bar_arrive, 0u);
            __threadfence();
            g_bar_gen = gen + 1u;
        } else {
            while (g_bar_gen == gen) { }
            __threadfence();
        }
    }
    __syncthreads();
}

__global__ __launch_bounds__(256, 2)
void k_fused(const float* __restrict__ X,
             const int* __restrict__ row_ids,
             const int* __restrict__ col_ids,
             const float* __restrict__ W1, const float* __restrict__ b1,
             const float* __restrict__ W2, const float* __restrict__ b2,
             const float* __restrict__ W3, const float* __restrict__ b3,
             float* __restrict__ out) {
    __shared__ float xs[DIO];      // 4 KB   (phase 3)
    __shared__ float h1p[800];     // 3.2 KB
    __shared__ float h2p[1000];    // 4 KB
    __shared__ float h1[HID];
    __shared__ float h2[HID];

    const int t = threadIdx.x;
    const int warp = t >> 5, lane = t & 31;

    // ---------------- Phase A: boundaries via adjacent-diff (CTAs 0..31) ----
    if (blockIdx.x < 32) {
        const bool rowpass = (blockIdx.x < 16);
        const int  slice   = rowpass ? blockIdx.x : (blockIdx.x - 16);
        const int  nb  = rowpass ? RB : CB;
        const int  n   = rowpass ? NROWS : NCOLS;
        const int* ids = rowpass ? row_ids : col_ids;
        int*   bnd = rowpass ? g_rowb : g_colb;
        float* o   = out + DIO + (rowpass ? 0 : (RB + 1));
        const int i = slice * 512 + t * 2;
        #pragma unroll
        for (int d = 0; d < 2; d++) {
            int g = i + d;
            if (g < n) {
                int cur  = ids[g];
                int prev = (g == 0) ? -1 : ids[g - 1];
                for (int k = prev + 1; k <= cur; k++) { bnd[k] = g; o[k] = (float)g; }
                if (g == n - 1)
                    for (int k = cur + 1; k <= nb; k++) { bnd[k] = n; o[k] = (float)n; }
            }
        }
    }

    grid_barrier();

    // ---------------- Phase 1: row-block partial sums (all 256 CTAs) -------
    // CTA (rb = bid>>3, chunk = bid&7): column stripe of 256 float4,
    // thread owns ONE float4 column; sums contiguous row slab [rlo, rhi).
    {
        const int rb    = blockIdx.x >> 3;
        const int chunk = blockIdx.x & 7;
        const int rlo = g_rowb[rb], rhi = g_rowb[rb + 1];
        const int c4  = chunk * 256 + t;              // this thread's float4 column

        float4 acc = make_float4(0.f, 0.f, 0.f, 0.f);
        const float4* p = (const float4*)X + (size_t)rlo * NC4 + c4;

        int r = rlo;
        for (; r + 16 <= rhi; r += 16) {
            #pragma unroll
            for (int k = 0; k < 16; k++) {
                float4 v = p[k * NC4];                // LDG.128 [R + k*32KB]
                acc.x += v.x; acc.y += v.y; acc.z += v.z; acc.w += v.w;
            }
            p += 16 * NC4;
        }
        for (; r < rhi; r++) {
            float4 v = *p; p += NC4;
            acc.x += v.x; acc.y += v.y; acc.z += v.z; acc.w += v.w;
        }
        g_rowsum4[rb * NC4 + c4] = acc;               // sole owner: plain STG
    }

    grid_barrier();

    // ---------------- Phase 2: column-block reduce (CTAs 0..127) -----------
    // One warp per (rb, cb): rb = bid>>2, cb = (bid&3)*8 + warp.
    if (blockIdx.x < 128) {
        const int rb = blockIdx.x >> 2;
        const int cb = (blockIdx.x & 3) * 8 + warp;
        const int clo = g_colb[cb], chi = g_colb[cb + 1];
        const float* rs = (const float*)(g_rowsum4 + rb * NC4);

        float a0 = 0.f, a1 = 0.f, a2 = 0.f, a3 = 0.f;
        int j = clo + lane;
        for (; j + 96 < chi; j += 128) {              // 4 loads in flight
            a0 += rs[j]; a1 += rs[j + 32]; a2 += rs[j + 64]; a3 += rs[j + 96];
        }
        for (; j < chi; j += 32) a0 += rs[j];
        float a = (a0 + a1) + (a2 + a3);
        #pragma unroll
        for (int o = 16; o; o >>= 1) a += __shfl_xor_sync(0xFFFFFFFFu, a, o);
        if (lane == 0) g_blk[rb * CB + cb] = a;       // sole owner: plain STG
    }

    grid_barrier();

    // ---------------- Phase 3: MLP + sigmoid (CTA 0, 256 threads) ----------
    if (blockIdx.x != 0) return;

    #pragma unroll
    for (int d = 0; d < 4; d++) {
        int b = t + d * 256;
        int rb = b >> 5, cbi = b & 31;
        float rc = (float)(g_rowb[rb + 1] - g_rowb[rb]);
        float cc = (float)(g_colb[cbi + 1] - g_colb[cbi]);
        xs[b] = g_blk[b] / fmaxf(rc * cc, 1.0f);
    }
    __syncthreads();

    // layer 1: h1 = relu(x @ W1 + b1); 8 K-slices x 100 outputs = 800 units
    for (int u = t; u < 800; u += 256) {
        const int j  = u % HID;
        const int i0 = (u / HID) * 128;
        float acc = 0.f;
        #pragma unroll 16
        for (int i = 0; i < 128; i++)
            acc += xs[i0 + i] * W1[(size_t)(i0 + i) * HID + j];
        h1p[u] = acc;
    }
    __syncthreads();
    if (t < HID) {
        float a = b1[t];
        #pragma unroll
        for (int sl = 0; sl < 8; sl++) a += h1p[sl * HID + t];
        h1[t] = fmaxf(a, 0.f);
    }
    __syncthreads();

    // layer 2: h2 = relu(h1 @ W2 + b2); 10 K-slices x 100
    for (int u = t; u < 1000; u += 256) {
        const int j  = u % HID;
        const int i0 = (u / HID) * 10;
        float acc = 0.f;
        #pragma unroll
        for (int i = 0; i < 10; i++)
            acc += h1[i0 + i] * W2[(i0 + i) * HID + j];
        h2p[u] = acc;
    }
    __syncthreads();
    if (t < HID) {
        float a = b2[t];
        #pragma unroll
        for (int sl = 0; sl < 10; sl++) a += h2p[sl * HID + t];
        h2[t] = fmaxf(a, 0.f);
    }
    __syncthreads();

    // layer 3: out = sigmoid(h2 @ W3 + b3), W3[100,1024]
    #pragma unroll
    for (int d = 0; d < 4; d++) {
        int j = t + d * 256;
        float a = b3[j];
        #pragma unroll 10
        for (int i = 0; i < HID; i++) a += h2[i] * W3[(size_t)i * DIO + j];
        out[j] = 1.0f / (1.0f + __expf(-a));
    }
}

extern "C" void kernel_launch(void* const* d_in, const int* in_sizes, int n_in,
                              void* d_out, int out_size) {
    const float* X       = (const float*)d_in[0];
    const int*   row_ids = (const int*)  d_in[1];
    const int*   col_ids = (const int*)  d_in[2];
    const float* W1      = (const float*)d_in[3];
    const float* b1      = (const float*)d_in[4];
    const float* W2      = (const float*)d_in[5];
    const float* b2      = (const float*)d_in[6];
    const float* W3      = (const float*)d_in[7];
    const float* b3      = (const float*)d_in[8];
    float* out = (float*)d_out;

    k_fused<<<NB_CTAS, 256>>>(X, row_ids, col_ids, W1, b1, W2, b2, W3, b3, out);
}

// round 13
// speedup vs baseline: 1.8985x; 1.4221x over previous
#include <cuda_runtime.h>
#include <cuda_bf16.h>
#include <cstdint>
#include <cstddef>

// Problem constants (fixed by the reference)
#define NROWS 8192
#define NCOLS 8192
#define NC4   (NCOLS/4)                // 2048 float4 per row
#define RB 32
#define CB 32
#define HID 100
#define DIO (RB*CB)
#define RSPLIT 8                       // row-phase split per row-block
#define NB_CTAS 256                    // grid; all co-resident (2 CTAs/SM cap = 296)

// Scratch (no cudaMalloc allowed)
__device__ float4 g_rowsum4[RB * RSPLIT * NC4];  // 8 MB: per (rb, s) column sums
__device__ float  g_blk[DIO];
__device__ int    g_rowb[RB + 1];
__device__ int    g_colb[CB + 1];
__device__ unsigned g_bar_arrive = 0;
__device__ volatile unsigned g_bar_gen = 0;

// Generation-based grid barrier: safe across graph replays (self-resetting),
// deadlock-free because all NB_CTAS are co-resident (<=2 CTAs/SM).
__device__ __forceinline__ void grid_barrier() {
    __syncthreads();
    if (threadIdx.x == 0) {
        __threadfence();
        unsigned gen = g_bar_gen;
        unsigned a = atomicAdd(&g_bar_arrive, 1u);
        if (a == NB_CTAS - 1u) {
            atomicExch(&g_bar_arrive, 0u);
            __threadfence();
            g_bar_gen = gen + 1u;
        } else {
            while (g_bar_gen == gen) { }
            __threadfence();
        }
    }
    __syncthreads();
}

__global__ __launch_bounds__(256, 2)
void k_fused(const float* __restrict__ X,
             const int* __restrict__ row_ids,
             const int* __restrict__ col_ids,
             const float* __restrict__ W1, const float* __restrict__ b1,
             const float* __restrict__ W2, const float* __restrict__ b2,
             const float* __restrict__ W3, const float* __restrict__ b3,
             float* __restrict__ out) {
    __shared__ float xs[DIO];
    __shared__ float h1p[800];
    __shared__ float h2p[1000];
    __shared__ float h1[HID];
    __shared__ float h2[HID];

    const int t = threadIdx.x;
    const int warp = t >> 5, lane = t & 31;

    // ---------------- Phase A: boundaries via adjacent-diff (CTAs 0..31) ----
    if (blockIdx.x < 32) {
        const bool rowpass = (blockIdx.x < 16);
        const int  slice   = rowpass ? blockIdx.x : (blockIdx.x - 16);
        const int  nb  = rowpass ? RB : CB;
        const int  n   = rowpass ? NROWS : NCOLS;
        const int* ids = rowpass ? row_ids : col_ids;
        int*   bnd = rowpass ? g_rowb : g_colb;
        float* o   = out + DIO + (rowpass ? 0 : (RB + 1));
        const int i = slice * 512 + t * 2;
        #pragma unroll
        for (int d = 0; d < 2; d++) {
            int g = i + d;
            if (g < n) {
                int cur  = ids[g];
                int prev = (g == 0) ? -1 : ids[g - 1];
                for (int k = prev + 1; k <= cur; k++) { bnd[k] = g; o[k] = (float)g; }
                if (g == n - 1)
                    for (int k = cur + 1; k <= nb; k++) { bnd[k] = n; o[k] = (float)n; }
            }
        }
    }

    grid_barrier();

    // ---------------- Phase 1: sequential full-row partial sums ------------
    // CTA (rb = bid>>3, s = bid&7): rows rlo+s, rlo+s+8, ... Each row is read
    // as ONE contiguous 32KB burst: thread t loads float4 columns t+256p,
    // p=0..7 (8 independent LDG.128.CS in flight), accumulating into 8
    // register float4s. Sole-owner store into (rb,s) slice afterwards.
    {
        const int rb = blockIdx.x >> 3;
        const int s  = blockIdx.x & 7;
        const int rlo = g_rowb[rb], rhi = g_rowb[rb + 1];

        float4 acc[8];
        #pragma unroll
        for (int p = 0; p < 8; p++) acc[p] = make_float4(0.f, 0.f, 0.f, 0.f);

        for (int r = rlo + s; r < rhi; r += RSPLIT) {
            const float4* row = (const float4*)X + (size_t)r * NC4;
            #pragma unroll
            for (int p = 0; p < 8; p++) {
                float4 v = __ldcs(row + t + 256 * p);    // streaming, read-once
                acc[p].x += v.x; acc[p].y += v.y;
                acc[p].z += v.z; acc[p].w += v.w;
            }
        }

        float4* dst = g_rowsum4 + ((size_t)(rb * RSPLIT + s)) * NC4;
        #pragma unroll
        for (int p = 0; p < 8; p++) dst[t + 256 * p] = acc[p];
    }

    grid_barrier();

    // ---------------- Phase 2: column-block reduce (CTAs 0..127) -----------
    // One warp per (rb, cb): rb = bid>>2, cb = (bid&3)*8 + warp.
    // Sums over the 8 s-slices and the column range [clo, chi).
    if (blockIdx.x < 128) {
        const int rb = blockIdx.x >> 2;
        const int cb = (blockIdx.x & 3) * 8 + warp;
        const int clo = g_colb[cb], chi = g_colb[cb + 1];
        const float* base = (const float*)(g_rowsum4 + (size_t)rb * RSPLIT * NC4);

        float a = 0.f;
        for (int j = clo + lane; j < chi; j += 32) {
            float p0 = 0.f, p1 = 0.f, p2 = 0.f, p3 = 0.f;
            #pragma unroll
            for (int s = 0; s < 8; s += 4) {             // 8 loads in flight
                p0 += base[(s    ) * NCOLS + j];
                p1 += base[(s + 1) * NCOLS + j];
                p2 += base[(s + 2) * NCOLS + j];
                p3 += base[(s + 3) * NCOLS + j];
            }
            a += (p0 + p1) + (p2 + p3);
        }
        #pragma unroll
        for (int o = 16; o; o >>= 1) a += __shfl_xor_sync(0xFFFFFFFFu, a, o);
        if (lane == 0) g_blk[rb * CB + cb] = a;          // sole owner
    }

    grid_barrier();

    // ---------------- Phase 3: MLP + sigmoid (CTA 0, 256 threads) ----------
    if (blockIdx.x != 0) return;

    #pragma unroll
    for (int d = 0; d < 4; d++) {
        int b = t + d * 256;
        int rb = b >> 5, cbi = b & 31;
        float rc = (float)(g_rowb[rb + 1] - g_rowb[rb]);
        float cc = (float)(g_colb[cbi + 1] - g_colb[cbi]);
        xs[b] = g_blk[b] / fmaxf(rc * cc, 1.0f);
    }
    __syncthreads();

    // layer 1: h1 = relu(x @ W1 + b1); 8 K-slices x 100 outputs
    for (int u = t; u < 800; u += 256) {
        const int j  = u % HID;
        const int i0 = (u / HID) * 128;
        float acc = 0.f;
        #pragma unroll 16
        for (int i = 0; i < 128; i++)
            acc += xs[i0 + i] * W1[(size_t)(i0 + i) * HID + j];
        h1p[u] = acc;
    }
    __syncthreads();
    if (t < HID) {
        float a = b1[t];
        #pragma unroll
        for (int sl = 0; sl < 8; sl++) a += h1p[sl * HID + t];
        h1[t] = fmaxf(a, 0.f);
    }
    __syncthreads();

    // layer 2: h2 = relu(h1 @ W2 + b2); 10 K-slices x 100
    for (int u = t; u < 1000; u += 256) {
        const int j  = u % HID;
        const int i0 = (u / HID) * 10;
        float acc = 0.f;
        #pragma unroll
        for (int i = 0; i < 10; i++)
            acc += h1[i0 + i] * W2[(i0 + i) * HID + j];
        h2p[u] = acc;
    }
    __syncthreads();
    if (t < HID) {
        float a = b2[t];
        #pragma unroll
        for (int sl = 0; sl < 10; sl++) a += h2p[sl * HID + t];
        h2[t] = fmaxf(a, 0.f);
    }
    __syncthreads();

    // layer 3: out = sigmoid(h2 @ W3 + b3), W3[100,1024]
    #pragma unroll
    for (int d = 0; d < 4; d++) {
        int j = t + d * 256;
        float a = b3[j];
        #pragma unroll 10
        for (int i = 0; i < HID; i++) a += h2[i] * W3[(size_t)i * DIO + j];
        out[j] = 1.0f / (1.0f + __expf(-a));
    }
}

extern "C" void kernel_launch(void* const* d_in, const int* in_sizes, int n_in,
                              void* d_out, int out_size) {
    const float* X       = (const float*)d_in[0];
    const int*   row_ids = (const int*)  d_in[1];
    const int*   col_ids = (const int*)  d_in[2];
    const float* W1      = (const float*)d_in[3];
    const float* b1      = (const float*)d_in[4];
    const float* W2      = (const float*)d_in[5];
    const float* b2      = (const float*)d_in[6];
    const float* W3      = (const float*)d_in[7];
    const float* b3      = (const float*)d_in[8];
    float* out = (float*)d_out;

    k_fused<<<NB_CTAS, 256>>>(X, row_ids, col_ids, W1, b1, W2, b2, W3, b3, out);
}